// round 7
// baseline (speedup 1.0000x reference)
#include <cuda_runtime.h>
#include <cuda_fp16.h>
#include <cstdint>

#define BB 2
#define TT 8192
#define DD 1024
#define MM (BB*TT)
#define PCH 128
#define TCH (TT/PCH)

// ----------------------------- device scratch ------------------------------
__device__ __align__(128) __half g_Xh[(size_t)MM*DD];
__device__ __align__(128) __half g_Wvh[DD*DD];
__device__ __align__(128) __half g_Woh[DD*DD];
__device__ __align__(128) __half g_V[(size_t)MM*DD];
__device__ __align__(128) float2 g_part[BB*PCH*DD];
__device__ __align__(128) __half g_Rh[(size_t)MM*DD];

// ------------------------------ PTX helpers --------------------------------
__device__ __forceinline__ uint32_t smem_to_u32(const void* p) {
    uint32_t a;
    asm("{ .reg .u64 t; cvta.to.shared.u64 t, %1; cvt.u32.u64 %0, t; }" : "=r"(a) : "l"(p));
    return a;
}
#define SWZ(o) ((uint32_t)(o) ^ ((((uint32_t)(o)) >> 3) & 0x70))

#define CP_ASYNC16(dst, src) \
    asm volatile("cp.async.cg.shared.global [%0], [%1], 16;" :: "r"(dst), "l"(src))
#define CP_COMMIT() asm volatile("cp.async.commit_group;" ::: "memory")
#define CP_WAIT1() asm volatile("cp.async.wait_group 1;" ::: "memory")
#define CP_WAIT0() asm volatile("cp.async.wait_group 0;" ::: "memory")

#define LDMX4(r0, r1, r2, r3, addr) \
    asm volatile("ldmatrix.sync.aligned.m8n8.x4.shared.b16 {%0,%1,%2,%3}, [%4];" \
        : "=r"(r0), "=r"(r1), "=r"(r2), "=r"(r3) : "r"(addr))

#define MMA16816(d, a, b) \
    asm volatile("mma.sync.aligned.m16n8k16.row.col.f32.f16.f16.f32 " \
        "{%0,%1,%2,%3}, {%4,%5,%6,%7}, {%8,%9}, {%0,%1,%2,%3};" \
        : "+f"((d)[0]), "+f"((d)[1]), "+f"((d)[2]), "+f"((d)[3]) \
        : "r"((a)[0]), "r"((a)[1]), "r"((a)[2]), "r"((a)[3]), \
          "r"((b)[0]), "r"((b)[1]))

// ------------------------------- split -------------------------------------
__global__ void k_split(const float* __restrict__ in, int which) {
    size_t n; __half* hi;
    if (which == 0)      { n = (size_t)MM * DD; hi = g_Xh;  }
    else if (which == 1) { n = (size_t)DD * DD; hi = g_Wvh; }
    else                 { n = (size_t)DD * DD; hi = g_Woh; }
    size_t n4 = n >> 2;
    const float4* in4 = (const float4*)in;
    __half2* h2 = (__half2*)hi;
    for (size_t i = (size_t)blockIdx.x * blockDim.x + threadIdx.x; i < n4;
         i += (size_t)gridDim.x * blockDim.x) {
        float4 v = in4[i];
        __half2 a, b;
        a.x = __float2half(v.x); a.y = __float2half(v.y);
        b.x = __float2half(v.z); b.y = __float2half(v.w);
        h2[2*i] = a; h2[2*i+1] = b;
    }
}

// -------------------------------- GEMM -------------------------------------
// C[m,n] = sum_k A[m,k]*B[n,k], fp16 x fp16 -> fp32 accumulate.
// 3-stage cp.async pipeline, ONE __syncthreads per K-chunk:
//   wait_group 1  -> chunk c resident (for this thread)
//   __syncthreads -> chunk c visible to all; stage (c-1)%3 fully consumed
//   issue chunk c+2 into stage (c+2)%3  (== (c-1)%3, now free)
//   compute chunk c from stage c%3
#define TILEB 16384          // 128 rows x 128B
#define STAGEB 32768         // A tile + B tile per stage
#define GSMEM  98304         // 3 stages
#define NCHUNK 16

__global__ void __launch_bounds__(256, 2)
k_gemm(int which, float* __restrict__ outC) {
    extern __shared__ __align__(1024) char smem[];
    const __half *Ah, *Bh;
    if (which == 0) { Ah = g_Xh; Bh = g_Wvh; }
    else            { Ah = g_Rh; Bh = g_Woh; }

    const uint32_t sb = smem_to_u32(smem);
    const int tid = threadIdx.x, wid = tid >> 5, lid = tid & 31;
    const int warp_m = wid & 3, warp_n = wid >> 2;
    const int tn = blockIdx.x * 128, tm = blockIdx.y * 128;

    float acc[2][8][4];
    #pragma unroll
    for (int mi = 0; mi < 2; ++mi)
        #pragma unroll
        for (int ni = 0; ni < 8; ++ni)
            #pragma unroll
            for (int q = 0; q < 4; ++q) acc[mi][ni][q] = 0.f;

    auto load_chunk = [&](int c, int stage) {
        const int k0 = c << 6;
        const char* srcA = (const char*)(Ah + (size_t)tm * DD + k0);
        const char* srcB = (const char*)(Bh + (size_t)tn * DD + k0);
        const uint32_t dA = sb + stage * STAGEB;
        const uint32_t dB = dA + TILEB;
        #pragma unroll
        for (int i = 0; i < 4; ++i) {
            int j = tid + i * 256;
            int row = j >> 3, seg = j & 7;
            uint32_t off = SWZ((row << 7) | (seg << 4));
            size_t goff = (size_t)row * (DD * 2) + seg * 16;
            CP_ASYNC16(dA + off, srcA + goff);
            CP_ASYNC16(dB + off, srcB + goff);
        }
        CP_COMMIT();
    };

    load_chunk(0, 0);
    load_chunk(1, 1);

    const int a_row = warp_m * 32 + (lid & 7) + ((lid >> 3) & 1) * 8;
    const int a_kof = ((lid >> 4) & 1) * 8;
    const int b_row = warp_n * 64 + (lid & 7) + ((lid >> 4) & 1) * 8;
    const int b_kof = ((lid >> 3) & 1) * 8;

    int stage = 0;
    for (int c = 0; c < NCHUNK; ++c) {
        if (c == NCHUNK - 1) CP_WAIT0(); else CP_WAIT1();
        __syncthreads();
        if (c + 2 < NCHUNK) {
            int s2 = stage + 2; if (s2 >= 3) s2 -= 3;
            load_chunk(c + 2, s2);
        }

        const uint32_t aB = sb + stage * STAGEB;
        const uint32_t bB = aB + TILEB;
        #pragma unroll
        for (int kk = 0; kk < 4; ++kk) {
            uint32_t af[2][4], bf[8][2];
            #pragma unroll
            for (int mi = 0; mi < 2; ++mi) {
                uint32_t addr = aB + SWZ(((a_row + mi * 16) << 7) | ((a_kof + kk * 16) << 1));
                LDMX4(af[mi][0], af[mi][1], af[mi][2], af[mi][3], addr);
            }
            #pragma unroll
            for (int ni = 0; ni < 4; ++ni) {
                uint32_t r0, r1, r2, r3;
                uint32_t addr = bB + SWZ(((b_row + ni * 16) << 7) | ((b_kof + kk * 16) << 1));
                LDMX4(r0, r1, r2, r3, addr);
                bf[2*ni][0] = r0; bf[2*ni][1] = r1;
                bf[2*ni+1][0] = r2; bf[2*ni+1][1] = r3;
            }
            #pragma unroll
            for (int mi = 0; mi < 2; ++mi)
                #pragma unroll
                for (int ni = 0; ni < 8; ++ni)
                    MMA16816(acc[mi][ni], af[mi], bf[ni]);
        }
        if (++stage >= 3) stage = 0;
    }

    if (which == 0) {
        #pragma unroll
        for (int mi = 0; mi < 2; ++mi) {
            int m = tm + warp_m * 32 + mi * 16 + (lid >> 2);
            int n0 = tn + warp_n * 64 + (lid & 3) * 2;
            __half* r0p = g_V + (size_t)m * DD + n0;
            __half* r1p = g_V + (size_t)(m + 8) * DD + n0;
            #pragma unroll
            for (int ni = 0; ni < 8; ++ni) {
                __half2 v0, v1;
                v0.x = __float2half(acc[mi][ni][0]); v0.y = __float2half(acc[mi][ni][1]);
                v1.x = __float2half(acc[mi][ni][2]); v1.y = __float2half(acc[mi][ni][3]);
                *(__half2*)(r0p + ni * 8) = v0;
                *(__half2*)(r1p + ni * 8) = v1;
            }
        }
    } else {
        #pragma unroll
        for (int mi = 0; mi < 2; ++mi) {
            int m = tm + warp_m * 32 + mi * 16 + (lid >> 2);
            int n0 = tn + warp_n * 64 + (lid & 3) * 2;
            float* r0p = outC + (size_t)m * DD + n0;
            float* r1p = outC + (size_t)(m + 8) * DD + n0;
            #pragma unroll
            for (int ni = 0; ni < 8; ++ni) {
                *(float2*)(r0p + ni * 8) = make_float2(acc[mi][ni][0], acc[mi][ni][1]);
                *(float2*)(r1p + ni * 8) = make_float2(acc[mi][ni][2], acc[mi][ni][3]);
            }
        }
    }
}

// ------------------------------- scan --------------------------------------
// ph = fl32(t*f) (exact reproduction of reference rounding), then 3-term fp32
// Cody-Waite reduction (q<=8192 13-bit, H 6-bit mantissa -> q*H exact),
// MUFU sin/cos on |r|<=pi. Both batches b=0,1 share one rotor evaluation.
__device__ __forceinline__ void rot_sincos(float ph, float* s, float* c) {
    constexpr double TP = 6.283185307179586;
    constexpr float H = 6.28125f;
    constexpr float Mv = (float)(TP - (double)H);
    constexpr float L  = (float)(TP - (double)H - (double)Mv);
    float q = rintf(ph * 0.15915494309189535f);
    float r = fmaf(q, -H, ph);
    r = fmaf(q, -Mv, r);
    r = fmaf(q, -L, r);
    *s = __sinf(r); *c = __cosf(r);
}

__global__ void k_pass1(const float* __restrict__ freqs) {
    const int ch = blockIdx.x, tid = threadIdx.x;
    float f[4]; float2 acc0[4], acc1[4];
    #pragma unroll
    for (int j = 0; j < 4; ++j) {
        f[j] = freqs[tid + j*256];
        acc0[j] = make_float2(0.f, 0.f);
        acc1[j] = make_float2(0.f, 0.f);
    }
    const __half* vp0 = g_V + ((size_t)ch * TCH) * DD + tid;
    const __half* vp1 = vp0 + (size_t)TT * DD;
    for (int tl = 0; tl < TCH; ++tl) {
        float t = (float)(ch * TCH + tl);
        #pragma unroll
        for (int j = 0; j < 4; ++j) {
            float s, c; rot_sincos(t * f[j], &s, &c);
            float v0 = __half2float(vp0[j*256]);
            float v1 = __half2float(vp1[j*256]);
            acc0[j].x += v0 * c; acc0[j].y += v0 * s;
            acc1[j].x += v1 * c; acc1[j].y += v1 * s;
        }
        vp0 += DD; vp1 += DD;
    }
    #pragma unroll
    for (int j = 0; j < 4; ++j) {
        g_part[(size_t)ch * DD + tid + j*256] = acc0[j];
        g_part[(size_t)(PCH + ch) * DD + tid + j*256] = acc1[j];
    }
}

__global__ void k_pass2() {
    int id = blockIdx.x * blockDim.x + threadIdx.x;   // 0..2047
    int b = id >> 10, d = id & 1023;
    float2 run = make_float2(0.f, 0.f);
    size_t base = (size_t)b * PCH * DD + d;
    for (int ch = 0; ch < PCH; ch += 4) {
        float2 v0 = g_part[base + (size_t)(ch+0)*DD];
        float2 v1 = g_part[base + (size_t)(ch+1)*DD];
        float2 v2 = g_part[base + (size_t)(ch+2)*DD];
        float2 v3 = g_part[base + (size_t)(ch+3)*DD];
        g_part[base + (size_t)(ch+0)*DD] = run; run.x += v0.x; run.y += v0.y;
        g_part[base + (size_t)(ch+1)*DD] = run; run.x += v1.x; run.y += v1.y;
        g_part[base + (size_t)(ch+2)*DD] = run; run.x += v2.x; run.y += v2.y;
        g_part[base + (size_t)(ch+3)*DD] = run; run.x += v3.x; run.y += v3.y;
    }
}

__global__ void k_pass3(const float* __restrict__ freqs) {
    const int ch = blockIdx.x, tid = threadIdx.x;
    float f[4]; float2 acc0[4], acc1[4];
    #pragma unroll
    for (int j = 0; j < 4; ++j) {
        f[j] = freqs[tid + j*256];
        acc0[j] = g_part[(size_t)ch * DD + tid + j*256];
        acc1[j] = g_part[(size_t)(PCH + ch) * DD + tid + j*256];
    }
    size_t base = ((size_t)ch * TCH) * DD + tid;
    const __half* vp0 = g_V + base;
    const __half* vp1 = vp0 + (size_t)TT * DD;
    __half* rh0 = g_Rh + base;
    __half* rh1 = rh0 + (size_t)TT * DD;
    for (int tl = 0; tl < TCH; ++tl) {
        float t = (float)(ch * TCH + tl);
        #pragma unroll
        for (int j = 0; j < 4; ++j) {
            float s, c; rot_sincos(t * f[j], &s, &c);
            float v0 = __half2float(vp0[j*256]);
            float v1 = __half2float(vp1[j*256]);
            acc0[j].x += v0 * c; acc0[j].y += v0 * s;
            acc1[j].x += v1 * c; acc1[j].y += v1 * s;
            rh0[j*256] = __float2half(acc0[j].x * c + acc0[j].y * s);
            rh1[j*256] = __float2half(acc1[j].x * c + acc1[j].y * s);
        }
        vp0 += DD; vp1 += DD; rh0 += DD; rh1 += DD;
    }
}

// ------------------------------- launch ------------------------------------
extern "C" void kernel_launch(void* const* d_in, const int* in_sizes, int n_in,
                              void* d_out, int out_size) {
    const float* x     = (const float*)d_in[0];
    const float* Wv    = (const float*)d_in[2];
    const float* Wo    = (const float*)d_in[3];
    const float* freqs = (const float*)d_in[4];
    float* out = (float*)d_out;

    static int smem_set = 0;
    if (!smem_set) {
        cudaFuncSetAttribute(k_gemm, cudaFuncAttributeMaxDynamicSharedMemorySize, GSMEM);
        smem_set = 1;
    }

    k_split<<<2048, 256>>>(x, 0);
    k_split<<<256, 256>>>(Wv, 1);
    k_split<<<256, 256>>>(Wo, 2);

    k_gemm<<<dim3(8, 128), 256, GSMEM>>>(0, nullptr);

    k_pass1<<<PCH, 256>>>(freqs);
    k_pass2<<<64, 32>>>();
    k_pass3<<<PCH, 256>>>(freqs);

    k_gemm<<<dim3(8, 128), 256, GSMEM>>>(1, out);
}

// round 8
// speedup vs baseline: 1.2172x; 1.2172x over previous
#include <cuda_runtime.h>
#include <cuda_fp16.h>
#include <cstdint>

#define BB 2
#define TT 8192
#define DD 1024
#define MM (BB*TT)
#define PCH 256
#define TCH (TT/PCH)     // 32

// ----------------------------- device scratch ------------------------------
__device__ __align__(128) __half g_Xh[(size_t)MM*DD];
__device__ __align__(128) __half g_Wvh[DD*DD];
__device__ __align__(128) __half g_Woh[DD*DD];
__device__ __align__(128) __half g_V[(size_t)MM*DD];
__device__ __align__(128) float2 g_part[(size_t)BB*PCH*DD];
__device__ __align__(128) __half g_Rh[(size_t)MM*DD];

// ------------------------------ PTX helpers --------------------------------
__device__ __forceinline__ uint32_t smem_to_u32(const void* p) {
    uint32_t a;
    asm("{ .reg .u64 t; cvta.to.shared.u64 t, %1; cvt.u32.u64 %0, t; }" : "=r"(a) : "l"(p));
    return a;
}
#define SWZ(o) ((uint32_t)(o) ^ ((((uint32_t)(o)) >> 3) & 0x70))

#define CP_ASYNC16(dst, src) \
    asm volatile("cp.async.cg.shared.global [%0], [%1], 16;" :: "r"(dst), "l"(src))
#define CP_COMMIT() asm volatile("cp.async.commit_group;" ::: "memory")
#define CP_WAIT1() asm volatile("cp.async.wait_group 1;" ::: "memory")
#define CP_WAIT0() asm volatile("cp.async.wait_group 0;" ::: "memory")

#define LDMX4(r0, r1, r2, r3, addr) \
    asm volatile("ldmatrix.sync.aligned.m8n8.x4.shared.b16 {%0,%1,%2,%3}, [%4];" \
        : "=r"(r0), "=r"(r1), "=r"(r2), "=r"(r3) : "r"(addr))

#define MMA16816(d, a, b) \
    asm volatile("mma.sync.aligned.m16n8k16.row.col.f32.f16.f16.f32 " \
        "{%0,%1,%2,%3}, {%4,%5,%6,%7}, {%8,%9}, {%0,%1,%2,%3};" \
        : "+f"((d)[0]), "+f"((d)[1]), "+f"((d)[2]), "+f"((d)[3]) \
        : "r"((a)[0]), "r"((a)[1]), "r"((a)[2]), "r"((a)[3]), \
          "r"((b)[0]), "r"((b)[1]))

// ------------------------------- split -------------------------------------
__global__ void k_split(const float* __restrict__ in, int which) {
    size_t n; __half* hi;
    if (which == 0)      { n = (size_t)MM * DD; hi = g_Xh;  }
    else if (which == 1) { n = (size_t)DD * DD; hi = g_Wvh; }
    else                 { n = (size_t)DD * DD; hi = g_Woh; }
    size_t n4 = n >> 2;
    const float4* in4 = (const float4*)in;
    __half2* h2 = (__half2*)hi;
    for (size_t i = (size_t)blockIdx.x * blockDim.x + threadIdx.x; i < n4;
         i += (size_t)gridDim.x * blockDim.x) {
        float4 v = in4[i];
        __half2 a, b;
        a.x = __float2half(v.x); a.y = __float2half(v.y);
        b.x = __float2half(v.z); b.y = __float2half(v.w);
        h2[2*i] = a; h2[2*i+1] = b;
    }
}

// -------------------------------- GEMM -------------------------------------
// C[m,n] = sum_k A[m,k]*B[n,k], fp16 x fp16 -> fp32 accumulate.
// R6 configuration (measured best: 83.3us, tensor=67.8%).
#define TILEB 16384          // 128 rows x 128B
#define B_BASE 32768
#define GSMEM 65536
#define NCHUNK 16

__global__ void __launch_bounds__(256, 2)
k_gemm(int which, float* __restrict__ outC) {
    extern __shared__ __align__(1024) char smem[];
    const __half *Ah, *Bh;
    if (which == 0) { Ah = g_Xh; Bh = g_Wvh; }
    else            { Ah = g_Rh; Bh = g_Woh; }

    const uint32_t sb = smem_to_u32(smem);
    const int tid = threadIdx.x, wid = tid >> 5, lid = tid & 31;
    const int warp_m = wid & 3, warp_n = wid >> 2;
    const int tn = blockIdx.x * 128, tm = blockIdx.y * 128;

    float acc[2][8][4];
    #pragma unroll
    for (int mi = 0; mi < 2; ++mi)
        #pragma unroll
        for (int ni = 0; ni < 8; ++ni)
            #pragma unroll
            for (int q = 0; q < 4; ++q) acc[mi][ni][q] = 0.f;

    auto load_chunk = [&](int c, int buf) {
        const int k0 = c << 6;
        const char* srcA = (const char*)(Ah + (size_t)tm * DD + k0);
        const char* srcB = (const char*)(Bh + (size_t)tn * DD + k0);
        const uint32_t dA = sb + buf * TILEB;
        const uint32_t dB = sb + B_BASE + buf * TILEB;
        #pragma unroll
        for (int i = 0; i < 4; ++i) {
            int j = tid + i * 256;
            int row = j >> 3, seg = j & 7;
            uint32_t off = SWZ((row << 7) | (seg << 4));
            size_t goff = (size_t)row * (DD * 2) + seg * 16;
            CP_ASYNC16(dA + off, srcA + goff);
            CP_ASYNC16(dB + off, srcB + goff);
        }
        CP_COMMIT();
    };

    load_chunk(0, 0);

    const int a_row = warp_m * 32 + (lid & 7) + ((lid >> 3) & 1) * 8;
    const int a_kof = ((lid >> 4) & 1) * 8;
    const int b_row = warp_n * 64 + (lid & 7) + ((lid >> 4) & 1) * 8;
    const int b_kof = ((lid >> 3) & 1) * 8;

    for (int c = 0; c < NCHUNK; ++c) {
        if (c + 1 < NCHUNK) { load_chunk(c + 1, (c + 1) & 1); CP_WAIT1(); }
        else                { CP_WAIT0(); }
        __syncthreads();

        const uint32_t aB = sb + (c & 1) * TILEB;
        const uint32_t bB = sb + B_BASE + (c & 1) * TILEB;
        #pragma unroll
        for (int kk = 0; kk < 4; ++kk) {
            uint32_t af[2][4], bf[8][2];
            #pragma unroll
            for (int mi = 0; mi < 2; ++mi) {
                uint32_t addr = aB + SWZ(((a_row + mi * 16) << 7) | ((a_kof + kk * 16) << 1));
                LDMX4(af[mi][0], af[mi][1], af[mi][2], af[mi][3], addr);
            }
            #pragma unroll
            for (int ni = 0; ni < 4; ++ni) {
                uint32_t r0, r1, r2, r3;
                uint32_t addr = bB + SWZ(((b_row + ni * 16) << 7) | ((b_kof + kk * 16) << 1));
                LDMX4(r0, r1, r2, r3, addr);
                bf[2*ni][0] = r0; bf[2*ni][1] = r1;
                bf[2*ni+1][0] = r2; bf[2*ni+1][1] = r3;
            }
            #pragma unroll
            for (int mi = 0; mi < 2; ++mi)
                #pragma unroll
                for (int ni = 0; ni < 8; ++ni)
                    MMA16816(acc[mi][ni], af[mi], bf[ni]);
        }
        __syncthreads();
    }

    if (which == 0) {
        #pragma unroll
        for (int mi = 0; mi < 2; ++mi) {
            int m = tm + warp_m * 32 + mi * 16 + (lid >> 2);
            int n0 = tn + warp_n * 64 + (lid & 3) * 2;
            __half* r0p = g_V + (size_t)m * DD + n0;
            __half* r1p = g_V + (size_t)(m + 8) * DD + n0;
            #pragma unroll
            for (int ni = 0; ni < 8; ++ni) {
                __half2 v0, v1;
                v0.x = __float2half(acc[mi][ni][0]); v0.y = __float2half(acc[mi][ni][1]);
                v1.x = __float2half(acc[mi][ni][2]); v1.y = __float2half(acc[mi][ni][3]);
                *(__half2*)(r0p + ni * 8) = v0;
                *(__half2*)(r1p + ni * 8) = v1;
            }
        }
    } else {
        #pragma unroll
        for (int mi = 0; mi < 2; ++mi) {
            int m = tm + warp_m * 32 + mi * 16 + (lid >> 2);
            int n0 = tn + warp_n * 64 + (lid & 3) * 2;
            float* r0p = outC + (size_t)m * DD + n0;
            float* r1p = outC + (size_t)(m + 8) * DD + n0;
            #pragma unroll
            for (int ni = 0; ni < 8; ++ni) {
                *(float2*)(r0p + ni * 8) = make_float2(acc[mi][ni][0], acc[mi][ni][1]);
                *(float2*)(r1p + ni * 8) = make_float2(acc[mi][ni][2], acc[mi][ni][3]);
            }
        }
    }
}

// ------------------------------- scan --------------------------------------
// ph = fl32(t*f) (exact reproduction of reference rounding), then 3-term fp32
// Cody-Waite reduction (q<=8192 13-bit, H 6-bit mantissa -> q*H exact),
// MUFU sin/cos on |r|<=pi. Each block handles one time-chunk for BOTH batches
// (rotor shared), with 256 chunks to keep 256 blocks resident.
// Thread owns d in {2*tid, 2*tid+1, 512+2*tid, 512+2*tid+1} -> half2 access.
__device__ __forceinline__ void rot_sincos(float ph, float* s, float* c) {
    constexpr double TP = 6.283185307179586;
    constexpr float H = 6.28125f;
    constexpr float Mv = (float)(TP - (double)H);
    constexpr float L  = (float)(TP - (double)H - (double)Mv);
    float q = rintf(ph * 0.15915494309189535f);
    float r = fmaf(q, -H, ph);
    r = fmaf(q, -Mv, r);
    r = fmaf(q, -L, r);
    *s = __sinf(r); *c = __cosf(r);
}

__global__ void k_pass1(const float* __restrict__ freqs) {
    const int ch = blockIdx.x, tid = threadIdx.x;
    float2 f[2];
    f[0] = *(const float2*)(freqs + 2*tid);
    f[1] = *(const float2*)(freqs + 512 + 2*tid);
    float2 a0[2][2], a1[2][2];   // [jj][d-pair-elem], batch 0 / 1
    #pragma unroll
    for (int jj = 0; jj < 2; ++jj)
        #pragma unroll
        for (int e = 0; e < 2; ++e) {
            a0[jj][e] = make_float2(0.f, 0.f);
            a1[jj][e] = make_float2(0.f, 0.f);
        }
    const __half2* vp0 = (const __half2*)(g_V + (size_t)ch * TCH * DD) + tid;
    const __half2* vp1 = vp0 + (size_t)TT * DD / 2;
    for (int tl = 0; tl < TCH; ++tl) {
        float t = (float)(ch * TCH + tl);
        #pragma unroll
        for (int jj = 0; jj < 2; ++jj) {
            float sx, cx, sy, cy;
            rot_sincos(t * f[jj].x, &sx, &cx);
            rot_sincos(t * f[jj].y, &sy, &cy);
            float2 v0 = __half22float2(vp0[jj * 256]);
            float2 v1 = __half22float2(vp1[jj * 256]);
            a0[jj][0].x += v0.x * cx; a0[jj][0].y += v0.x * sx;
            a0[jj][1].x += v0.y * cy; a0[jj][1].y += v0.y * sy;
            a1[jj][0].x += v1.x * cx; a1[jj][0].y += v1.x * sx;
            a1[jj][1].x += v1.y * cy; a1[jj][1].y += v1.y * sy;
        }
        vp0 += DD / 2; vp1 += DD / 2;
    }
    #pragma unroll
    for (int jj = 0; jj < 2; ++jj) {
        int d = jj * 512 + 2 * tid;
        *(float4*)&g_part[(size_t)ch * DD + d] = *(float4*)&a0[jj][0];
        *(float4*)&g_part[(size_t)(PCH + ch) * DD + d] = *(float4*)&a1[jj][0];
    }
}

__global__ void k_pass2() {
    int id = blockIdx.x * blockDim.x + threadIdx.x;   // 0..2047
    int b = id >> 10, d = id & 1023;
    float2 run = make_float2(0.f, 0.f);
    size_t base = (size_t)b * PCH * DD + d;
    for (int ch = 0; ch < PCH; ch += 8) {
        float2 v[8];
        #pragma unroll
        for (int u = 0; u < 8; ++u) v[u] = g_part[base + (size_t)(ch + u) * DD];
        #pragma unroll
        for (int u = 0; u < 8; ++u) {
            g_part[base + (size_t)(ch + u) * DD] = run;
            run.x += v[u].x; run.y += v[u].y;
        }
    }
}

__global__ void k_pass3(const float* __restrict__ freqs) {
    const int ch = blockIdx.x, tid = threadIdx.x;
    float2 f[2];
    f[0] = *(const float2*)(freqs + 2*tid);
    f[1] = *(const float2*)(freqs + 512 + 2*tid);
    float2 a0[2][2], a1[2][2];
    #pragma unroll
    for (int jj = 0; jj < 2; ++jj) {
        int d = jj * 512 + 2 * tid;
        *(float4*)&a0[jj][0] = *(float4*)&g_part[(size_t)ch * DD + d];
        *(float4*)&a1[jj][0] = *(float4*)&g_part[(size_t)(PCH + ch) * DD + d];
    }
    const __half2* vp0 = (const __half2*)(g_V + (size_t)ch * TCH * DD) + tid;
    const __half2* vp1 = vp0 + (size_t)TT * DD / 2;
    __half2* rh0 = (__half2*)(g_Rh + (size_t)ch * TCH * DD) + tid;
    __half2* rh1 = rh0 + (size_t)TT * DD / 2;
    for (int tl = 0; tl < TCH; ++tl) {
        float t = (float)(ch * TCH + tl);
        #pragma unroll
        for (int jj = 0; jj < 2; ++jj) {
            float sx, cx, sy, cy;
            rot_sincos(t * f[jj].x, &sx, &cx);
            rot_sincos(t * f[jj].y, &sy, &cy);
            float2 v0 = __half22float2(vp0[jj * 256]);
            float2 v1 = __half22float2(vp1[jj * 256]);
            a0[jj][0].x += v0.x * cx; a0[jj][0].y += v0.x * sx;
            a0[jj][1].x += v0.y * cy; a0[jj][1].y += v0.y * sy;
            a1[jj][0].x += v1.x * cx; a1[jj][0].y += v1.x * sx;
            a1[jj][1].x += v1.y * cy; a1[jj][1].y += v1.y * sy;
            __half2 r0, r1;
            r0.x = __float2half(a0[jj][0].x * cx + a0[jj][0].y * sx);
            r0.y = __float2half(a0[jj][1].x * cy + a0[jj][1].y * sy);
            r1.x = __float2half(a1[jj][0].x * cx + a1[jj][0].y * sx);
            r1.y = __float2half(a1[jj][1].x * cy + a1[jj][1].y * sy);
            rh0[jj * 256] = r0;
            rh1[jj * 256] = r1;
        }
        vp0 += DD / 2; vp1 += DD / 2; rh0 += DD / 2; rh1 += DD / 2;
    }
}

// ------------------------------- launch ------------------------------------
extern "C" void kernel_launch(void* const* d_in, const int* in_sizes, int n_in,
                              void* d_out, int out_size) {
    const float* x     = (const float*)d_in[0];
    const float* Wv    = (const float*)d_in[2];
    const float* Wo    = (const float*)d_in[3];
    const float* freqs = (const float*)d_in[4];
    float* out = (float*)d_out;

    static int smem_set = 0;
    if (!smem_set) {
        cudaFuncSetAttribute(k_gemm, cudaFuncAttributeMaxDynamicSharedMemorySize, GSMEM);
        smem_set = 1;
    }

    k_split<<<2048, 256>>>(x, 0);
    k_split<<<256, 256>>>(Wv, 1);
    k_split<<<256, 256>>>(Wo, 2);

    k_gemm<<<dim3(8, 128), 256, GSMEM>>>(0, nullptr);

    k_pass1<<<PCH, 256>>>(freqs);
    k_pass2<<<64, 32>>>();
    k_pass3<<<PCH, 256>>>(freqs);

    k_gemm<<<dim3(8, 128), 256, GSMEM>>>(1, out);
}